// round 2
// baseline (speedup 1.0000x reference)
#include <cuda_runtime.h>
#include <cstdint>

#define HASH_SIZE (1u << 19)
#define HASH_MASK (HASH_SIZE - 1u)
#define PRIME_X 73856093u
#define PRIME_Y 19349663u
#define DIM 32

// One position row = 32 floats = 8 float4 = 128 bytes.
// 8 threads cooperate per position: thread j moves float4 #j of the row.
__global__ void hashgrid_gather_kernel(const float2* __restrict__ positions,
                                       const float4* __restrict__ table,
                                       float4* __restrict__ out,
                                       int n) {
    int gid = blockIdx.x * blockDim.x + threadIdx.x;
    int row = gid >> 3;          // position index
    int part = gid & 7;          // which float4 of the 32-float row
    if (row >= n) return;

    float2 p = positions[row];   // broadcast load across the 8-thread group
    // positions are uniform in [0, 4096); floorf is exact, values non-negative.
    uint32_t ix = (uint32_t)(int)floorf(p.x);
    uint32_t iy = (uint32_t)(int)floorf(p.y);
    // Low 19 bits of the int64 products depend only on low 32 bits -> uint32 math is exact.
    uint32_t h = ((ix * PRIME_X) ^ (iy * PRIME_Y)) & HASH_MASK;

    out[(size_t)row * 8 + part] = __ldg(&table[(size_t)h * 8 + part]);
}

extern "C" void kernel_launch(void* const* d_in, const int* in_sizes, int n_in,
                              void* d_out, int out_size) {
    const float2* positions = (const float2*)d_in[0];   // [N, 2] float32
    const float4* table     = (const float4*)d_in[1];   // [HASH_SIZE, 32] float32
    float4* out             = (float4*)d_out;           // [N, 32] float32

    int n = in_sizes[0] / 2;    // N positions
    long long total_threads = (long long)n * 8;
    int block = 256;
    int grid = (int)((total_threads + block - 1) / block);

    hashgrid_gather_kernel<<<grid, block>>>(positions, table, out, n);
}

// round 3
// speedup vs baseline: 1.3809x; 1.3809x over previous
#include <cuda_runtime.h>
#include <cstdint>

#define HASH_SIZE (1u << 19)
#define HASH_MASK (HASH_SIZE - 1u)
#define PRIME_X 73856093u
#define PRIME_Y 19349663u
#define UNROLL 4

// One position row = 32 floats = 8 float4 = 128 bytes.
// 8 threads cooperate per row: thread j moves float4 #j.
// Each thread handles UNROLL rows (strided by total group count) so that
// 4 independent position loads + 4 independent gathers are in flight
// simultaneously -> MLP ~4x vs the single-row version.
__global__ void hashgrid_gather_kernel(const float2* __restrict__ positions,
                                       const float4* __restrict__ table,
                                       float4* __restrict__ out,
                                       int n) {
    int gid     = blockIdx.x * blockDim.x + threadIdx.x;
    int part    = gid & 7;
    int group   = gid >> 3;
    int ngroups = (gridDim.x * blockDim.x) >> 3;

    int      r[UNROLL];
    float2   p[UNROLL];
    uint32_t h[UNROLL];
    float4   v[UNROLL];

    // Phase 1: batch all position loads (independent -> front-batched LDGs)
    #pragma unroll
    for (int u = 0; u < UNROLL; u++) {
        r[u] = group + u * ngroups;
        if (r[u] < n) p[u] = __ldg(&positions[r[u]]);
    }

    // Phase 2: hashes (ALU only). Low 19 bits of the int64 products depend
    // only on the low 32 bits -> uint32 math reproduces the reference exactly.
    // floorf is exact for uniform [0, 4096) positions.
    #pragma unroll
    for (int u = 0; u < UNROLL; u++) {
        uint32_t ix = (uint32_t)(int)floorf(p[u].x);
        uint32_t iy = (uint32_t)(int)floorf(p[u].y);
        h[u] = ((ix * PRIME_X) ^ (iy * PRIME_Y)) & HASH_MASK;
    }

    // Phase 3: batch all gathers (independent, mostly L2 hits)
    #pragma unroll
    for (int u = 0; u < UNROLL; u++) {
        if (r[u] < n) v[u] = __ldg(&table[(size_t)h[u] * 8 + part]);
    }

    // Phase 4: coalesced stores
    #pragma unroll
    for (int u = 0; u < UNROLL; u++) {
        if (r[u] < n) out[(size_t)r[u] * 8 + part] = v[u];
    }
}

extern "C" void kernel_launch(void* const* d_in, const int* in_sizes, int n_in,
                              void* d_out, int out_size) {
    const float2* positions = (const float2*)d_in[0];   // [N, 2] float32
    const float4* table     = (const float4*)d_in[1];   // [HASH_SIZE, 32] float32
    float4* out             = (float4*)d_out;           // [N, 32] float32

    int n = in_sizes[0] / 2;                 // N positions
    int ngroups = (n + UNROLL - 1) / UNROLL; // position groups (rows per thread-slot)
    long long total_threads = (long long)ngroups * 8;
    int block = 256;
    int grid = (int)((total_threads + block - 1) / block);

    hashgrid_gather_kernel<<<grid, block>>>(positions, table, out, n);
}